// round 10
// baseline (speedup 1.0000x reference)
#include <cuda_runtime.h>
#include <math.h>

#define MASK  0x7FFFFu
#define P1    2654435761u
#define P2    805459861u
#define NPTS_MAX (1 << 20)
#define NB   32768         // 32^3 Morton buckets (~32 pts/bucket)

typedef unsigned long long ull;

struct Params {
    float icell[16];   // res/2  (u = (x+1) * icell)
    float resm1[16];   // res-1 as float (clamp ceiling)
};

// ---------------- scratch (static device arrays; no runtime alloc) ----------
__device__ unsigned d_hist[NB];
__device__ unsigned d_offs[NB];
__device__ unsigned d_part[128];
__device__ unsigned d_rank[NPTS_MAX];         // original index -> sorted slot
__device__ float4   d_xs[NPTS_MAX];           // sorted points
__device__ float    d_scratch[NPTS_MAX * 32]; // sorted-order output lines (128MB)

// ---------------- helpers ---------------------------------------------------
__device__ __forceinline__ ull pk2(float a, float b) {
    ull r;
    asm("mov.b64 %0, {%1, %2};" : "=l"(r) : "f"(a), "f"(b));
    return r;
}

// packed lerp: a + t*(b-a) on two f32 lanes (sm_100+ f32x2 ops)
__device__ __forceinline__ ull lerp2(ull a, ull b, ull t) {
    ull d, r;
    asm("sub.rn.f32x2 %0, %1, %2;" : "=l"(d) : "l"(b), "l"(a));
    asm("fma.rn.f32x2 %0, %1, %2, %3;" : "=l"(r) : "l"(t), "l"(d), "l"(a));
    return r;
}

__device__ __forceinline__ unsigned expand_bits5(unsigned v) {
    // spread 5 bits: abcde -> a__b__c__d__e (3-apart)
    v &= 0x1Fu;
    v = (v | (v << 8)) & 0x0100F0u;
    v = (v | (v << 4)) & 0x10C30Cu;
    v = (v | (v << 2)) & 0x249249u;
    return v;
}

__device__ __forceinline__ unsigned bucket_key(float px, float py, float pz) {
    const float s = 16.0f;   // [-1,1] -> [0,32)
    int ix = min(max(__float2int_rd(fmaf(px, s, s)), 0), 31);
    int iy = min(max(__float2int_rd(fmaf(py, s, s)), 0), 31);
    int iz = min(max(__float2int_rd(fmaf(pz, s, s)), 0), 31);
    return expand_bits5((unsigned)ix) | (expand_bits5((unsigned)iy) << 1)
         | (expand_bits5((unsigned)iz) << 2);
}

// ---------------- sorting kernels -------------------------------------------
__global__ void k_hist(const float* __restrict__ x, int n) {
    int p = blockIdx.x * 256 + threadIdx.x;
    if (p >= n) return;
    float px = x[3 * p], py = x[3 * p + 1], pz = x[3 * p + 2];
    atomicAdd(&d_hist[bucket_key(px, py, pz)], 1u);
}

// parallel 3-phase exclusive scan of d_hist -> d_offs (NB = 128 * 256)
__global__ void k_scan1() {   // grid 128 x 256: block partial sums
    __shared__ unsigned sh[256];
    unsigned base = blockIdx.x * 256u;
    sh[threadIdx.x] = d_hist[base + threadIdx.x];
    __syncthreads();
    for (int s = 128; s > 0; s >>= 1) {
        if ((int)threadIdx.x < s) sh[threadIdx.x] += sh[threadIdx.x + s];
        __syncthreads();
    }
    if (threadIdx.x == 0) d_part[blockIdx.x] = sh[0];
}

__global__ void k_scan2() {   // 1 block x 128: exclusive scan of partials
    __shared__ unsigned sh[128];
    unsigned t = threadIdx.x;
    unsigned v = d_part[t];
    sh[t] = v;
    __syncthreads();
    for (int off = 1; off < 128; off <<= 1) {
        unsigned a = (t >= (unsigned)off) ? sh[t - off] : 0u;
        __syncthreads();
        sh[t] += a;
        __syncthreads();
    }
    d_part[t] = sh[t] - v;
}

__global__ void k_scan3() {   // grid 128 x 256: local exclusive scan + offset
    __shared__ unsigned sh[256];
    unsigned base = blockIdx.x * 256u;
    unsigned t = threadIdx.x;
    unsigned v = d_hist[base + t];
    sh[t] = v;
    __syncthreads();
    for (int off = 1; off < 256; off <<= 1) {
        unsigned a = (t >= (unsigned)off) ? sh[t - off] : 0u;
        __syncthreads();
        sh[t] += a;
        __syncthreads();
    }
    d_offs[base + t] = sh[t] - v + d_part[blockIdx.x];
}

__global__ void k_scatter(const float* __restrict__ x, int n) {
    int p = blockIdx.x * 256 + threadIdx.x;
    if (p >= n) return;
    float px = x[3 * p], py = x[3 * p + 1], pz = x[3 * p + 2];
    unsigned dst = atomicAdd(&d_offs[bucket_key(px, py, pz)], 1u);
    d_xs[dst]   = make_float4(px, py, pz, 0.0f);
    d_rank[p]   = dst;        // inverse map: original -> sorted slot
}

// ---------------- main kernel ------------------------------------------------
// Sorted gathers, zero smem (full L1D), coalesced stores to sorted scratch.
// No occupancy cap: kernel is L1-wavefront pipe-bound; 48 regs is fine.
__global__ __launch_bounds__(256) void hash_embed_kernel(
    const ull* __restrict__ tbl,    // tables as (level<<19) float2 entries
    int npts,
    Params prm)
{
    unsigned i = blockIdx.x * 256u + threadIdx.x;
    if (i >= (unsigned)npts) return;

    float4 v = d_xs[i];
    float px = v.x, py = v.y, pz = v.z;

    float* outp = d_scratch + (ull)i * 32u;
    ull res[4];

#pragma unroll
    for (int l = 0; l < 16; l++) {
        const float ic  = prm.icell[l];
        const float rm1 = prm.resm1[l];

        float ux = fmaf(px, ic, ic);
        float uy = fmaf(py, ic, ic);
        float uz = fmaf(pz, ic, ic);
        float fx = fminf(floorf(ux), rm1);
        float fy = fminf(floorf(uy), rm1);
        float fz = fminf(floorf(uz), rm1);
        float tx = ux - fx;
        float ty = uy - fy;
        float tz = uz - fz;

        unsigned ix0 = (unsigned)fx;
        unsigned iy0 = (unsigned)fy;
        unsigned iz0 = (unsigned)fz;
        unsigned hy0 = iy0 * P1;
        unsigned hy1 = hy0 + P1;
        unsigned hz0 = iz0 * P2;
        unsigned hz1 = hz0 + P2;

        unsigned r00 = hy0 ^ hz0;
        unsigned r10 = hy1 ^ hz0;
        unsigned r01 = hy0 ^ hz1;
        unsigned r11 = hy1 ^ hz1;

        unsigned h00 = (ix0 ^ r00) & MASK;
        unsigned h10 = (ix0 ^ r10) & MASK;
        unsigned h01 = (ix0 ^ r01) & MASK;
        unsigned h11 = (ix0 ^ r11) & MASK;

        const ull* tl = tbl + ((unsigned)l << 19);
        const ulonglong2* tp = (const ulonglong2*)tl;

        // one 16B L1-cached load covers the (ix0, ix0^1) vertex pair
        ulonglong2 q00 = __ldg(tp + (h00 >> 1));
        ulonglong2 q10 = __ldg(tp + (h10 >> 1));
        ulonglong2 q01 = __ldg(tp + (h01 >> 1));
        ulonglong2 q11 = __ldg(tp + (h11 >> 1));

        ull e000 = (h00 & 1) ? q00.y : q00.x;
        ull e010 = (h10 & 1) ? q10.y : q10.x;
        ull e001 = (h01 & 1) ? q01.y : q01.x;
        ull e011 = (h11 & 1) ? q11.y : q11.x;

        ull e100, e110, e101, e111;
        if (ix0 & 1) {
            unsigned ix1 = ix0 + 1u;
            e100 = __ldg(tl + ((ix1 ^ r00) & MASK));
            e110 = __ldg(tl + ((ix1 ^ r10) & MASK));
            e101 = __ldg(tl + ((ix1 ^ r01) & MASK));
            e111 = __ldg(tl + ((ix1 ^ r11) & MASK));
        } else {
            e100 = (h00 & 1) ? q00.x : q00.y;
            e110 = (h10 & 1) ? q10.x : q10.y;
            e101 = (h01 & 1) ? q01.x : q01.y;
            e111 = (h11 & 1) ? q11.x : q11.y;
        }

        ull t2x = pk2(tx, tx);
        ull t2y = pk2(ty, ty);
        ull t2z = pk2(tz, tz);

        ull a0 = lerp2(e000, e100, t2x);
        ull a1 = lerp2(e010, e110, t2x);
        ull a2 = lerp2(e001, e101, t2x);
        ull a3 = lerp2(e011, e111, t2x);
        ull b0 = lerp2(a0, a1, t2y);
        ull b1 = lerp2(a2, a3, t2y);
        res[l & 3] = lerp2(b0, b1, t2z);

        if ((l & 3) == 3) {
            int g = l >> 2;
            ulonglong2 v0 = make_ulonglong2(res[0], res[1]);
            ulonglong2 v1 = make_ulonglong2(res[2], res[3]);
            *reinterpret_cast<ulonglong2*>(outp + g * 8 + 0) = v0;
            *reinterpret_cast<ulonglong2*>(outp + g * 8 + 4) = v1;
        }
    }
}

// ---------------- permute: GATHER form --------------------------------------
// coalesced writes to out (sequential lines), random 128B-line READS from
// scratch (mostly L2-resident right after main kernel writes it).
__global__ __launch_bounds__(256) void k_permute(float* __restrict__ out, int n) {
    unsigned idx = blockIdx.x * 256u + threadIdx.x;   // one thread = 16B
    unsigned p = idx >> 3;          // original point (sequential -> coalesced out)
    unsigned f = idx & 7u;          // float4 slot within the 128B line
    if (p >= (unsigned)n) return;
    unsigned j = d_rank[p];         // 8 lanes share -> broadcast
    float4 v = __ldcs(reinterpret_cast<const float4*>(d_scratch + (ull)j * 32u + f * 4u));
    *reinterpret_cast<float4*>(out + (ull)p * 32u + f * 4u) = v;
}

// ---------------- launch ------------------------------------------------------
extern "C" void kernel_launch(void* const* d_in, const int* in_sizes, int n_in,
                              void* d_out, int out_size) {
    int xi = 0, ti = 1;
    if (n_in >= 2 && in_sizes[0] > in_sizes[1]) { xi = 1; ti = 0; }

    const float* x = (const float*)d_in[xi];
    const ull* tbl = (const ull*)d_in[ti];
    float* out = (float*)d_out;

    Params prm;
    double factor = exp((log(512.0) - log(16.0)) / 15.0);
    for (int i = 0; i < 16; i++) {
        double r = floor(16.0 * pow(factor, (double)i));
        prm.icell[i] = (float)(r * 0.5);
        prm.resm1[i] = (float)(r - 1.0);
    }

    int npts = in_sizes[xi] / 3;
    int pb = (npts + 255) / 256;

    void* histp = nullptr;
    cudaGetSymbolAddress(&histp, d_hist);
    cudaMemsetAsync(histp, 0, NB * sizeof(unsigned), 0);

    k_hist<<<pb, 256>>>(x, npts);
    k_scan1<<<NB / 256, 256>>>();
    k_scan2<<<1, 128>>>();
    k_scan3<<<NB / 256, 256>>>();
    k_scatter<<<pb, 256>>>(x, npts);
    hash_embed_kernel<<<pb, 256>>>(tbl, npts, prm);
    k_permute<<<(npts * 8 + 255) / 256, 256>>>(out, npts);
}

// round 11
// speedup vs baseline: 1.6610x; 1.6610x over previous
#include <cuda_runtime.h>
#include <math.h>

#define MASK  0x7FFFFu
#define P1    2654435761u
#define P2    805459861u
#define NPTS_MAX (1 << 20)
#define NB   32768         // 32^3 Morton buckets (~32 pts/bucket)

typedef unsigned long long ull;

struct Params {
    float icell[16];   // res/2  (u = (x+1) * icell)
    float resm1[16];   // res-1 as float (clamp ceiling)
};

// ---------------- scratch (static device arrays; no runtime alloc) ----------
__device__ unsigned d_hist[NB];
__device__ unsigned d_offs[NB];
__device__ unsigned d_part[128];
__device__ unsigned d_rank[NPTS_MAX];         // original index -> sorted slot
__device__ float4   d_xs[NPTS_MAX];           // sorted points
__device__ float    d_scratch[NPTS_MAX * 32]; // sorted-order output lines (128MB)

// ---------------- helpers ---------------------------------------------------
__device__ __forceinline__ ull pk2(float a, float b) {
    ull r;
    asm("mov.b64 %0, {%1, %2};" : "=l"(r) : "f"(a), "f"(b));
    return r;
}

// packed lerp: a + t*(b-a) on two f32 lanes (sm_100+ f32x2 ops)
__device__ __forceinline__ ull lerp2(ull a, ull b, ull t) {
    ull d, r;
    asm("sub.rn.f32x2 %0, %1, %2;" : "=l"(d) : "l"(b), "l"(a));
    asm("fma.rn.f32x2 %0, %1, %2, %3;" : "=l"(r) : "l"(t), "l"(d), "l"(a));
    return r;
}

// proven 10-bit Morton spread (works for any v <= 0x3FF, incl. 5-bit inputs)
__device__ __forceinline__ unsigned expand_bits(unsigned v) {
    v &= 0x3FFu;
    v = (v | (v << 16)) & 0x030000FFu;
    v = (v | (v << 8))  & 0x0300F00Fu;
    v = (v | (v << 4))  & 0x030C30C3u;
    v = (v | (v << 2))  & 0x09249249u;
    return v;
}

__device__ __forceinline__ unsigned bucket_key(float px, float py, float pz) {
    const float s = 16.0f;   // [-1,1] -> [0,32)
    int ix = min(max(__float2int_rd(fmaf(px, s, s)), 0), 31);
    int iy = min(max(__float2int_rd(fmaf(py, s, s)), 0), 31);
    int iz = min(max(__float2int_rd(fmaf(pz, s, s)), 0), 31);
    return expand_bits((unsigned)ix) | (expand_bits((unsigned)iy) << 1)
         | (expand_bits((unsigned)iz) << 2);
}

// ---------------- sorting kernels -------------------------------------------
__global__ void k_hist(const float* __restrict__ x, int n) {
    int p = blockIdx.x * 256 + threadIdx.x;
    if (p >= n) return;
    float px = x[3 * p], py = x[3 * p + 1], pz = x[3 * p + 2];
    atomicAdd(&d_hist[bucket_key(px, py, pz)], 1u);
}

// parallel 3-phase exclusive scan of d_hist -> d_offs (NB = 128 * 256)
__global__ void k_scan1() {   // grid 128 x 256: block partial sums
    __shared__ unsigned sh[256];
    unsigned base = blockIdx.x * 256u;
    sh[threadIdx.x] = d_hist[base + threadIdx.x];
    __syncthreads();
    for (int s = 128; s > 0; s >>= 1) {
        if ((int)threadIdx.x < s) sh[threadIdx.x] += sh[threadIdx.x + s];
        __syncthreads();
    }
    if (threadIdx.x == 0) d_part[blockIdx.x] = sh[0];
}

__global__ void k_scan2() {   // 1 block x 128: exclusive scan of partials
    __shared__ unsigned sh[128];
    unsigned t = threadIdx.x;
    unsigned v = d_part[t];
    sh[t] = v;
    __syncthreads();
    for (int off = 1; off < 128; off <<= 1) {
        unsigned a = (t >= (unsigned)off) ? sh[t - off] : 0u;
        __syncthreads();
        sh[t] += a;
        __syncthreads();
    }
    d_part[t] = sh[t] - v;
}

__global__ void k_scan3() {   // grid 128 x 256: local exclusive scan + offset
    __shared__ unsigned sh[256];
    unsigned base = blockIdx.x * 256u;
    unsigned t = threadIdx.x;
    unsigned v = d_hist[base + t];
    sh[t] = v;
    __syncthreads();
    for (int off = 1; off < 256; off <<= 1) {
        unsigned a = (t >= (unsigned)off) ? sh[t - off] : 0u;
        __syncthreads();
        sh[t] += a;
        __syncthreads();
    }
    d_offs[base + t] = sh[t] - v + d_part[blockIdx.x];
}

__global__ void k_scatter(const float* __restrict__ x, int n) {
    int p = blockIdx.x * 256 + threadIdx.x;
    if (p >= n) return;
    float px = x[3 * p], py = x[3 * p + 1], pz = x[3 * p + 2];
    unsigned dst = atomicAdd(&d_offs[bucket_key(px, py, pz)], 1u);
    d_xs[dst]   = make_float4(px, py, pz, 0.0f);
    d_rank[p]   = dst;        // inverse map: original -> sorted slot
}

// ---------------- main kernel ------------------------------------------------
// Sorted gathers, zero smem (full L1D), coalesced stores to sorted scratch.
__global__ __launch_bounds__(256) void hash_embed_kernel(
    const ull* __restrict__ tbl,    // tables as (level<<19) float2 entries
    int npts,
    Params prm)
{
    unsigned i = blockIdx.x * 256u + threadIdx.x;
    if (i >= (unsigned)npts) return;

    float4 v = d_xs[i];
    float px = v.x, py = v.y, pz = v.z;

    float* outp = d_scratch + (ull)i * 32u;
    ull res[4];

#pragma unroll
    for (int l = 0; l < 16; l++) {
        const float ic  = prm.icell[l];
        const float rm1 = prm.resm1[l];

        float ux = fmaf(px, ic, ic);
        float uy = fmaf(py, ic, ic);
        float uz = fmaf(pz, ic, ic);
        float fx = fminf(floorf(ux), rm1);
        float fy = fminf(floorf(uy), rm1);
        float fz = fminf(floorf(uz), rm1);
        float tx = ux - fx;
        float ty = uy - fy;
        float tz = uz - fz;

        unsigned ix0 = (unsigned)fx;
        unsigned iy0 = (unsigned)fy;
        unsigned iz0 = (unsigned)fz;
        unsigned hy0 = iy0 * P1;
        unsigned hy1 = hy0 + P1;
        unsigned hz0 = iz0 * P2;
        unsigned hz1 = hz0 + P2;

        unsigned r00 = hy0 ^ hz0;
        unsigned r10 = hy1 ^ hz0;
        unsigned r01 = hy0 ^ hz1;
        unsigned r11 = hy1 ^ hz1;

        unsigned h00 = (ix0 ^ r00) & MASK;
        unsigned h10 = (ix0 ^ r10) & MASK;
        unsigned h01 = (ix0 ^ r01) & MASK;
        unsigned h11 = (ix0 ^ r11) & MASK;

        const ull* tl = tbl + ((unsigned)l << 19);
        const ulonglong2* tp = (const ulonglong2*)tl;

        // one 16B L1-cached load covers the (ix0, ix0^1) vertex pair
        ulonglong2 q00 = __ldg(tp + (h00 >> 1));
        ulonglong2 q10 = __ldg(tp + (h10 >> 1));
        ulonglong2 q01 = __ldg(tp + (h01 >> 1));
        ulonglong2 q11 = __ldg(tp + (h11 >> 1));

        ull e000 = (h00 & 1) ? q00.y : q00.x;
        ull e010 = (h10 & 1) ? q10.y : q10.x;
        ull e001 = (h01 & 1) ? q01.y : q01.x;
        ull e011 = (h11 & 1) ? q11.y : q11.x;

        ull e100, e110, e101, e111;
        if (ix0 & 1) {
            unsigned ix1 = ix0 + 1u;
            e100 = __ldg(tl + ((ix1 ^ r00) & MASK));
            e110 = __ldg(tl + ((ix1 ^ r10) & MASK));
            e101 = __ldg(tl + ((ix1 ^ r01) & MASK));
            e111 = __ldg(tl + ((ix1 ^ r11) & MASK));
        } else {
            e100 = (h00 & 1) ? q00.x : q00.y;
            e110 = (h10 & 1) ? q10.x : q10.y;
            e101 = (h01 & 1) ? q01.x : q01.y;
            e111 = (h11 & 1) ? q11.x : q11.y;
        }

        ull t2x = pk2(tx, tx);
        ull t2y = pk2(ty, ty);
        ull t2z = pk2(tz, tz);

        ull a0 = lerp2(e000, e100, t2x);
        ull a1 = lerp2(e010, e110, t2x);
        ull a2 = lerp2(e001, e101, t2x);
        ull a3 = lerp2(e011, e111, t2x);
        ull b0 = lerp2(a0, a1, t2y);
        ull b1 = lerp2(a2, a3, t2y);
        res[l & 3] = lerp2(b0, b1, t2z);

        if ((l & 3) == 3) {
            int g = l >> 2;
            ulonglong2 v0 = make_ulonglong2(res[0], res[1]);
            ulonglong2 v1 = make_ulonglong2(res[2], res[3]);
            *reinterpret_cast<ulonglong2*>(outp + g * 8 + 0) = v0;
            *reinterpret_cast<ulonglong2*>(outp + g * 8 + 4) = v1;
        }
    }
}

// ---------------- permute: GATHER form --------------------------------------
// coalesced writes to out (sequential lines), random 128B-line READS from
// scratch (mostly L2-resident right after main kernel writes it).
__global__ __launch_bounds__(256) void k_permute(float* __restrict__ out, int n) {
    unsigned idx = blockIdx.x * 256u + threadIdx.x;   // one thread = 16B
    unsigned p = idx >> 3;          // original point (sequential -> coalesced out)
    unsigned f = idx & 7u;          // float4 slot within the 128B line
    if (p >= (unsigned)n) return;
    unsigned j = d_rank[p];         // 8 lanes share -> broadcast
    float4 v = __ldcs(reinterpret_cast<const float4*>(d_scratch + (ull)j * 32u + f * 4u));
    *reinterpret_cast<float4*>(out + (ull)p * 32u + f * 4u) = v;
}

// ---------------- launch ------------------------------------------------------
extern "C" void kernel_launch(void* const* d_in, const int* in_sizes, int n_in,
                              void* d_out, int out_size) {
    int xi = 0, ti = 1;
    if (n_in >= 2 && in_sizes[0] > in_sizes[1]) { xi = 1; ti = 0; }

    const float* x = (const float*)d_in[xi];
    const ull* tbl = (const ull*)d_in[ti];
    float* out = (float*)d_out;

    Params prm;
    double factor = exp((log(512.0) - log(16.0)) / 15.0);
    for (int i = 0; i < 16; i++) {
        double r = floor(16.0 * pow(factor, (double)i));
        prm.icell[i] = (float)(r * 0.5);
        prm.resm1[i] = (float)(r - 1.0);
    }

    int npts = in_sizes[xi] / 3;
    int pb = (npts + 255) / 256;

    void* histp = nullptr;
    cudaGetSymbolAddress(&histp, d_hist);
    cudaMemsetAsync(histp, 0, NB * sizeof(unsigned), 0);

    k_hist<<<pb, 256>>>(x, npts);
    k_scan1<<<NB / 256, 256>>>();
    k_scan2<<<1, 128>>>();
    k_scan3<<<NB / 256, 256>>>();
    k_scatter<<<pb, 256>>>(x, npts);
    hash_embed_kernel<<<pb, 256>>>(tbl, npts, prm);
    k_permute<<<(npts * 8 + 255) / 256, 256>>>(out, npts);
}

// round 12
// speedup vs baseline: 1.7017x; 1.0245x over previous
#include <cuda_runtime.h>
#include <math.h>

#define MASK  0x7FFFFu
#define P1    2654435761u
#define P2    805459861u
#define NPTS_MAX (1 << 20)
#define NB   262144        // 64^3 Morton buckets (validated optimum)

typedef unsigned long long ull;

struct Params {
    float icell[16];   // res/2  (u = (x+1) * icell)
    float resm1[16];   // res-1 as float (clamp ceiling)
};

// ---------------- scratch (static device arrays; no runtime alloc) ----------
__device__ unsigned d_hist[NB];
__device__ unsigned d_offs[NB];
__device__ unsigned d_part[1024];
__device__ unsigned d_rank[NPTS_MAX];         // original index -> sorted slot
__device__ float4   d_xs[NPTS_MAX];           // sorted points
__device__ float    d_scratch[NPTS_MAX * 32]; // sorted-order output lines (128MB)

// ---------------- helpers ---------------------------------------------------
__device__ __forceinline__ ull pk2(float a, float b) {
    ull r;
    asm("mov.b64 %0, {%1, %2};" : "=l"(r) : "f"(a), "f"(b));
    return r;
}

// packed lerp: a + t*(b-a) on two f32 lanes (sm_100+ f32x2 ops)
__device__ __forceinline__ ull lerp2(ull a, ull b, ull t) {
    ull d, r;
    asm("sub.rn.f32x2 %0, %1, %2;" : "=l"(d) : "l"(b), "l"(a));
    asm("fma.rn.f32x2 %0, %1, %2, %3;" : "=l"(r) : "l"(t), "l"(d), "l"(a));
    return r;
}

__device__ __forceinline__ ulonglong2 ldg2_cg(const ulonglong2* p) {
    ulonglong2 r;
    asm("ld.global.cg.v2.u64 {%0,%1}, [%2];" : "=l"(r.x), "=l"(r.y) : "l"(p));
    return r;
}
__device__ __forceinline__ ull ldg1_cg(const ull* p) {
    ull r;
    asm("ld.global.cg.u64 %0, [%1];" : "=l"(r) : "l"(p));
    return r;
}

__device__ __forceinline__ unsigned expand_bits(unsigned v) {
    v &= 0x3FFu;
    v = (v | (v << 16)) & 0x030000FFu;
    v = (v | (v << 8))  & 0x0300F00Fu;
    v = (v | (v << 4))  & 0x030C30C3u;
    v = (v | (v << 2))  & 0x09249249u;
    return v;
}

__device__ __forceinline__ unsigned bucket_key(float px, float py, float pz) {
    const float s = 32.0f;   // [-1,1] -> [0,64)
    int ix = min(max(__float2int_rd(fmaf(px, s, s)), 0), 63);
    int iy = min(max(__float2int_rd(fmaf(py, s, s)), 0), 63);
    int iz = min(max(__float2int_rd(fmaf(pz, s, s)), 0), 63);
    return expand_bits((unsigned)ix) | (expand_bits((unsigned)iy) << 1)
         | (expand_bits((unsigned)iz) << 2);
}

// ---------------- sorting kernels -------------------------------------------
__global__ void k_hist(const float* __restrict__ x, int n) {
    int p = blockIdx.x * 256 + threadIdx.x;
    if (p >= n) return;
    float px = x[3 * p], py = x[3 * p + 1], pz = x[3 * p + 2];
    atomicAdd(&d_hist[bucket_key(px, py, pz)], 1u);
}

// parallel 3-phase exclusive scan of d_hist -> d_offs (NB = 1024 * 256)
__global__ void k_scan1() {   // grid 1024 x 256: block partial sums
    __shared__ unsigned sh[256];
    unsigned base = blockIdx.x * 256u;
    sh[threadIdx.x] = d_hist[base + threadIdx.x];
    __syncthreads();
    for (int s = 128; s > 0; s >>= 1) {
        if ((int)threadIdx.x < s) sh[threadIdx.x] += sh[threadIdx.x + s];
        __syncthreads();
    }
    if (threadIdx.x == 0) d_part[blockIdx.x] = sh[0];
}

__global__ void k_scan2() {   // 1 block x 1024: exclusive scan of partials
    __shared__ unsigned sh[1024];
    unsigned t = threadIdx.x;
    unsigned v = d_part[t];
    sh[t] = v;
    __syncthreads();
    for (int off = 1; off < 1024; off <<= 1) {
        unsigned a = (t >= (unsigned)off) ? sh[t - off] : 0u;
        __syncthreads();
        sh[t] += a;
        __syncthreads();
    }
    d_part[t] = sh[t] - v;
}

__global__ void k_scan3() {   // grid 1024 x 256: local exclusive scan + offset
    __shared__ unsigned sh[256];
    unsigned base = blockIdx.x * 256u;
    unsigned t = threadIdx.x;
    unsigned v = d_hist[base + t];
    sh[t] = v;
    __syncthreads();
    for (int off = 1; off < 256; off <<= 1) {
        unsigned a = (t >= (unsigned)off) ? sh[t - off] : 0u;
        __syncthreads();
        sh[t] += a;
        __syncthreads();
    }
    d_offs[base + t] = sh[t] - v + d_part[blockIdx.x];
}

__global__ void k_scatter(const float* __restrict__ x, int n) {
    int p = blockIdx.x * 256 + threadIdx.x;
    if (p >= n) return;
    float px = x[3 * p], py = x[3 * p + 1], pz = x[3 * p + 2];
    unsigned dst = atomicAdd(&d_offs[bucket_key(px, py, pz)], 1u);
    d_xs[dst]   = make_float4(px, py, pz, 0.0f);
    d_rank[p]   = dst;        // inverse map: original -> sorted slot
}

// ---------------- main kernel ------------------------------------------------
// Sorted gathers, zero smem (full L1D), coalesced stores to sorted scratch.
// Levels 13-15 (zero-reuse random lines) bypass L1 (.cg) to protect the
// coarse/mid-level L1 working set.
__global__ __launch_bounds__(256) void hash_embed_kernel(
    const ull* __restrict__ tbl,    // tables as (level<<19) float2 entries
    int npts,
    Params prm)
{
    unsigned i = blockIdx.x * 256u + threadIdx.x;
    if (i >= (unsigned)npts) return;

    float4 v = d_xs[i];
    float px = v.x, py = v.y, pz = v.z;

    float* outp = d_scratch + (ull)i * 32u;
    ull res[4];

#pragma unroll
    for (int l = 0; l < 16; l++) {
        const float ic  = prm.icell[l];
        const float rm1 = prm.resm1[l];

        float ux = fmaf(px, ic, ic);
        float uy = fmaf(py, ic, ic);
        float uz = fmaf(pz, ic, ic);
        float fx = fminf(floorf(ux), rm1);
        float fy = fminf(floorf(uy), rm1);
        float fz = fminf(floorf(uz), rm1);
        float tx = ux - fx;
        float ty = uy - fy;
        float tz = uz - fz;

        unsigned ix0 = (unsigned)fx;
        unsigned iy0 = (unsigned)fy;
        unsigned iz0 = (unsigned)fz;
        unsigned hy0 = iy0 * P1;
        unsigned hy1 = hy0 + P1;
        unsigned hz0 = iz0 * P2;
        unsigned hz1 = hz0 + P2;

        unsigned r00 = hy0 ^ hz0;
        unsigned r10 = hy1 ^ hz0;
        unsigned r01 = hy0 ^ hz1;
        unsigned r11 = hy1 ^ hz1;

        unsigned h00 = (ix0 ^ r00) & MASK;
        unsigned h10 = (ix0 ^ r10) & MASK;
        unsigned h01 = (ix0 ^ r01) & MASK;
        unsigned h11 = (ix0 ^ r11) & MASK;

        const ull* tl = tbl + ((unsigned)l << 19);
        const ulonglong2* tp = (const ulonglong2*)tl;

        // one 16B load covers the (ix0, ix0^1) vertex pair
        ulonglong2 q00, q10, q01, q11;
        if (l >= 13) {     // zero-reuse levels: keep them out of L1
            q00 = ldg2_cg(tp + (h00 >> 1));
            q10 = ldg2_cg(tp + (h10 >> 1));
            q01 = ldg2_cg(tp + (h01 >> 1));
            q11 = ldg2_cg(tp + (h11 >> 1));
        } else {
            q00 = __ldg(tp + (h00 >> 1));
            q10 = __ldg(tp + (h10 >> 1));
            q01 = __ldg(tp + (h01 >> 1));
            q11 = __ldg(tp + (h11 >> 1));
        }

        ull e000 = (h00 & 1) ? q00.y : q00.x;
        ull e010 = (h10 & 1) ? q10.y : q10.x;
        ull e001 = (h01 & 1) ? q01.y : q01.x;
        ull e011 = (h11 & 1) ? q11.y : q11.x;

        ull e100, e110, e101, e111;
        if (ix0 & 1) {
            unsigned ix1 = ix0 + 1u;
            if (l >= 13) {
                e100 = ldg1_cg(tl + ((ix1 ^ r00) & MASK));
                e110 = ldg1_cg(tl + ((ix1 ^ r10) & MASK));
                e101 = ldg1_cg(tl + ((ix1 ^ r01) & MASK));
                e111 = ldg1_cg(tl + ((ix1 ^ r11) & MASK));
            } else {
                e100 = __ldg(tl + ((ix1 ^ r00) & MASK));
                e110 = __ldg(tl + ((ix1 ^ r10) & MASK));
                e101 = __ldg(tl + ((ix1 ^ r01) & MASK));
                e111 = __ldg(tl + ((ix1 ^ r11) & MASK));
            }
        } else {
            e100 = (h00 & 1) ? q00.x : q00.y;
            e110 = (h10 & 1) ? q10.x : q10.y;
            e101 = (h01 & 1) ? q01.x : q01.y;
            e111 = (h11 & 1) ? q11.x : q11.y;
        }

        ull t2x = pk2(tx, tx);
        ull t2y = pk2(ty, ty);
        ull t2z = pk2(tz, tz);

        ull a0 = lerp2(e000, e100, t2x);
        ull a1 = lerp2(e010, e110, t2x);
        ull a2 = lerp2(e001, e101, t2x);
        ull a3 = lerp2(e011, e111, t2x);
        ull b0 = lerp2(a0, a1, t2y);
        ull b1 = lerp2(a2, a3, t2y);
        res[l & 3] = lerp2(b0, b1, t2z);

        if ((l & 3) == 3) {
            int g = l >> 2;
            ulonglong2 v0 = make_ulonglong2(res[0], res[1]);
            ulonglong2 v1 = make_ulonglong2(res[2], res[3]);
            *reinterpret_cast<ulonglong2*>(outp + g * 8 + 0) = v0;
            *reinterpret_cast<ulonglong2*>(outp + g * 8 + 4) = v1;
        }
    }
}

// ---------------- permute: GATHER form --------------------------------------
// coalesced writes to out (sequential lines), random 128B-line READS from
// scratch (each 8-lane group reads one full line -> fully pipelined).
__global__ __launch_bounds__(256) void k_permute(float* __restrict__ out, int n) {
    unsigned idx = blockIdx.x * 256u + threadIdx.x;   // one thread = 16B
    unsigned p = idx >> 3;          // original point (sequential -> coalesced out)
    unsigned f = idx & 7u;          // float4 slot within the 128B line
    if (p >= (unsigned)n) return;
    unsigned j = d_rank[p];         // 8 lanes share -> broadcast
    float4 v = __ldcs(reinterpret_cast<const float4*>(d_scratch + (ull)j * 32u + f * 4u));
    *reinterpret_cast<float4*>(out + (ull)p * 32u + f * 4u) = v;
}

// ---------------- launch ------------------------------------------------------
extern "C" void kernel_launch(void* const* d_in, const int* in_sizes, int n_in,
                              void* d_out, int out_size) {
    int xi = 0, ti = 1;
    if (n_in >= 2 && in_sizes[0] > in_sizes[1]) { xi = 1; ti = 0; }

    const float* x = (const float*)d_in[xi];
    const ull* tbl = (const ull*)d_in[ti];
    float* out = (float*)d_out;

    Params prm;
    double factor = exp((log(512.0) - log(16.0)) / 15.0);
    for (int i = 0; i < 16; i++) {
        double r = floor(16.0 * pow(factor, (double)i));
        prm.icell[i] = (float)(r * 0.5);
        prm.resm1[i] = (float)(r - 1.0);
    }

    int npts = in_sizes[xi] / 3;
    int pb = (npts + 255) / 256;

    void* histp = nullptr;
    cudaGetSymbolAddress(&histp, d_hist);
    cudaMemsetAsync(histp, 0, NB * sizeof(unsigned), 0);

    k_hist<<<pb, 256>>>(x, npts);
    k_scan1<<<NB / 256, 256>>>();
    k_scan2<<<1, 1024>>>();
    k_scan3<<<NB / 256, 256>>>();
    k_scatter<<<pb, 256>>>(x, npts);
    hash_embed_kernel<<<pb, 256>>>(tbl, npts, prm);
    k_permute<<<(npts * 8 + 255) / 256, 256>>>(out, npts);
}

// round 13
// speedup vs baseline: 1.7573x; 1.0327x over previous
#include <cuda_runtime.h>
#include <math.h>

#define MASK  0x7FFFFu
#define P1    2654435761u
#define P2    805459861u
#define NPTS_MAX (1 << 20)
#define NB   262144        // 64^3 Morton buckets (validated optimum)

typedef unsigned long long ull;

struct Params {
    float icell[16];   // res/2  (u = (x+1) * icell)
    float resm1[16];   // res-1 as float (clamp ceiling)
};

// ---------------- scratch (static device arrays; no runtime alloc) ----------
__device__ unsigned d_hist[NB];
__device__ unsigned d_offs[NB];
__device__ unsigned d_part[1024];
__device__ unsigned d_rank[NPTS_MAX];         // original index -> sorted slot
__device__ float4   d_xs[NPTS_MAX];           // sorted points
__device__ float    d_scratch[NPTS_MAX * 32]; // sorted-order output lines (128MB)

// ---------------- helpers ---------------------------------------------------
__device__ __forceinline__ ull pk2(float a, float b) {
    ull r;
    asm("mov.b64 %0, {%1, %2};" : "=l"(r) : "f"(a), "f"(b));
    return r;
}

// packed lerp: a + t*(b-a) on two f32 lanes (sm_100+ f32x2 ops)
__device__ __forceinline__ ull lerp2(ull a, ull b, ull t) {
    ull d, r;
    asm("sub.rn.f32x2 %0, %1, %2;" : "=l"(d) : "l"(b), "l"(a));
    asm("fma.rn.f32x2 %0, %1, %2, %3;" : "=l"(r) : "l"(t), "l"(d), "l"(a));
    return r;
}

__device__ __forceinline__ unsigned expand_bits(unsigned v) {
    v &= 0x3FFu;
    v = (v | (v << 16)) & 0x030000FFu;
    v = (v | (v << 8))  & 0x0300F00Fu;
    v = (v | (v << 4))  & 0x030C30C3u;
    v = (v | (v << 2))  & 0x09249249u;
    return v;
}

__device__ __forceinline__ unsigned bucket_key(float px, float py, float pz) {
    const float s = 32.0f;   // [-1,1] -> [0,64)
    int ix = min(max(__float2int_rd(fmaf(px, s, s)), 0), 63);
    int iy = min(max(__float2int_rd(fmaf(py, s, s)), 0), 63);
    int iz = min(max(__float2int_rd(fmaf(pz, s, s)), 0), 63);
    return expand_bits((unsigned)ix) | (expand_bits((unsigned)iy) << 1)
         | (expand_bits((unsigned)iz) << 2);
}

// ---------------- sorting kernels -------------------------------------------
__global__ void k_hist(const float* __restrict__ x, int n) {
    int p = blockIdx.x * 256 + threadIdx.x;
    if (p >= n) return;
    float px = x[3 * p], py = x[3 * p + 1], pz = x[3 * p + 2];
    atomicAdd(&d_hist[bucket_key(px, py, pz)], 1u);
}

// 2-phase exclusive scan of d_hist -> d_offs (NB = 1024 * 256)
__global__ void k_scan1() {   // grid 1024 x 256: block partial sums
    __shared__ unsigned sh[256];
    unsigned base = blockIdx.x * 256u;
    sh[threadIdx.x] = d_hist[base + threadIdx.x];
    __syncthreads();
    for (int s = 128; s > 0; s >>= 1) {
        if ((int)threadIdx.x < s) sh[threadIdx.x] += sh[threadIdx.x + s];
        __syncthreads();
    }
    if (threadIdx.x == 0) d_part[blockIdx.x] = sh[0];
}

// fused: each block computes its own global prefix from d_part (L2-hot, 4KB)
// then does the local exclusive scan + offset.  Eliminates the k_scan2 launch.
__global__ void k_scan3() {   // grid 1024 x 256
    __shared__ unsigned sh[256];
    __shared__ unsigned red[256];
    unsigned base = blockIdx.x * 256u;
    unsigned t = threadIdx.x;

    // sum of d_part[0 .. blockIdx.x-1]: 256 threads, 4 strided elements each
    unsigned s = 0;
#pragma unroll
    for (int k = 0; k < 4; k++) {
        unsigned idx = t * 4u + k;
        if (idx < blockIdx.x) s += d_part[idx];
    }
    red[t] = s;
    __syncthreads();
    for (int st = 128; st > 0; st >>= 1) {
        if ((int)t < st) red[t] += red[t + st];
        __syncthreads();
    }
    unsigned block_base = red[0];

    // local exclusive scan of this block's 256 histogram entries
    unsigned v = d_hist[base + t];
    sh[t] = v;
    __syncthreads();
    for (int off = 1; off < 256; off <<= 1) {
        unsigned a = (t >= (unsigned)off) ? sh[t - off] : 0u;
        __syncthreads();
        sh[t] += a;
        __syncthreads();
    }
    d_offs[base + t] = sh[t] - v + block_base;
}

__global__ void k_scatter(const float* __restrict__ x, int n) {
    int p = blockIdx.x * 256 + threadIdx.x;
    if (p >= n) return;
    float px = x[3 * p], py = x[3 * p + 1], pz = x[3 * p + 2];
    unsigned dst = atomicAdd(&d_offs[bucket_key(px, py, pz)], 1u);
    d_xs[dst]   = make_float4(px, py, pz, 0.0f);
    d_rank[p]   = dst;        // inverse map: original -> sorted slot
}

// ---------------- main kernel ------------------------------------------------
// Sorted gathers, zero smem (full L1D), coalesced stores to sorted scratch.
// __ldg everywhere (validated: .cg on any level subset loses ~6us).
__global__ __launch_bounds__(256) void hash_embed_kernel(
    const ull* __restrict__ tbl,    // tables as (level<<19) float2 entries
    int npts,
    Params prm)
{
    unsigned i = blockIdx.x * 256u + threadIdx.x;
    if (i >= (unsigned)npts) return;

    float4 v = d_xs[i];
    float px = v.x, py = v.y, pz = v.z;

    float* outp = d_scratch + (ull)i * 32u;
    ull res[4];

#pragma unroll
    for (int l = 0; l < 16; l++) {
        const float ic  = prm.icell[l];
        const float rm1 = prm.resm1[l];

        float ux = fmaf(px, ic, ic);
        float uy = fmaf(py, ic, ic);
        float uz = fmaf(pz, ic, ic);
        float fx = fminf(floorf(ux), rm1);
        float fy = fminf(floorf(uy), rm1);
        float fz = fminf(floorf(uz), rm1);
        float tx = ux - fx;
        float ty = uy - fy;
        float tz = uz - fz;

        unsigned ix0 = (unsigned)fx;
        unsigned iy0 = (unsigned)fy;
        unsigned iz0 = (unsigned)fz;
        unsigned hy0 = iy0 * P1;
        unsigned hy1 = hy0 + P1;
        unsigned hz0 = iz0 * P2;
        unsigned hz1 = hz0 + P2;

        unsigned r00 = hy0 ^ hz0;
        unsigned r10 = hy1 ^ hz0;
        unsigned r01 = hy0 ^ hz1;
        unsigned r11 = hy1 ^ hz1;

        unsigned h00 = (ix0 ^ r00) & MASK;
        unsigned h10 = (ix0 ^ r10) & MASK;
        unsigned h01 = (ix0 ^ r01) & MASK;
        unsigned h11 = (ix0 ^ r11) & MASK;

        const ull* tl = tbl + ((unsigned)l << 19);
        const ulonglong2* tp = (const ulonglong2*)tl;

        // one 16B L1-cached load covers the (ix0, ix0^1) vertex pair
        ulonglong2 q00 = __ldg(tp + (h00 >> 1));
        ulonglong2 q10 = __ldg(tp + (h10 >> 1));
        ulonglong2 q01 = __ldg(tp + (h01 >> 1));
        ulonglong2 q11 = __ldg(tp + (h11 >> 1));

        ull e000 = (h00 & 1) ? q00.y : q00.x;
        ull e010 = (h10 & 1) ? q10.y : q10.x;
        ull e001 = (h01 & 1) ? q01.y : q01.x;
        ull e011 = (h11 & 1) ? q11.y : q11.x;

        ull e100, e110, e101, e111;
        if (ix0 & 1) {
            unsigned ix1 = ix0 + 1u;
            e100 = __ldg(tl + ((ix1 ^ r00) & MASK));
            e110 = __ldg(tl + ((ix1 ^ r10) & MASK));
            e101 = __ldg(tl + ((ix1 ^ r01) & MASK));
            e111 = __ldg(tl + ((ix1 ^ r11) & MASK));
        } else {
            e100 = (h00 & 1) ? q00.x : q00.y;
            e110 = (h10 & 1) ? q10.x : q10.y;
            e101 = (h01 & 1) ? q01.x : q01.y;
            e111 = (h11 & 1) ? q11.x : q11.y;
        }

        ull t2x = pk2(tx, tx);
        ull t2y = pk2(ty, ty);
        ull t2z = pk2(tz, tz);

        ull a0 = lerp2(e000, e100, t2x);
        ull a1 = lerp2(e010, e110, t2x);
        ull a2 = lerp2(e001, e101, t2x);
        ull a3 = lerp2(e011, e111, t2x);
        ull b0 = lerp2(a0, a1, t2y);
        ull b1 = lerp2(a2, a3, t2y);
        res[l & 3] = lerp2(b0, b1, t2z);

        if ((l & 3) == 3) {
            int g = l >> 2;
            ulonglong2 v0 = make_ulonglong2(res[0], res[1]);
            ulonglong2 v1 = make_ulonglong2(res[2], res[3]);
            *reinterpret_cast<ulonglong2*>(outp + g * 8 + 0) = v0;
            *reinterpret_cast<ulonglong2*>(outp + g * 8 + 4) = v1;
        }
    }
}

// ---------------- permute: GATHER form --------------------------------------
// coalesced writes to out (sequential lines), random 128B-line READS from
// scratch (each 8-lane group reads one full line -> fully pipelined).
__global__ __launch_bounds__(256) void k_permute(float* __restrict__ out, int n) {
    unsigned idx = blockIdx.x * 256u + threadIdx.x;   // one thread = 16B
    unsigned p = idx >> 3;          // original point (sequential -> coalesced out)
    unsigned f = idx & 7u;          // float4 slot within the 128B line
    if (p >= (unsigned)n) return;
    unsigned j = d_rank[p];         // 8 lanes share -> broadcast
    float4 v = __ldcs(reinterpret_cast<const float4*>(d_scratch + (ull)j * 32u + f * 4u));
    *reinterpret_cast<float4*>(out + (ull)p * 32u + f * 4u) = v;
}

// ---------------- launch ------------------------------------------------------
extern "C" void kernel_launch(void* const* d_in, const int* in_sizes, int n_in,
                              void* d_out, int out_size) {
    int xi = 0, ti = 1;
    if (n_in >= 2 && in_sizes[0] > in_sizes[1]) { xi = 1; ti = 0; }

    const float* x = (const float*)d_in[xi];
    const ull* tbl = (const ull*)d_in[ti];
    float* out = (float*)d_out;

    Params prm;
    double factor = exp((log(512.0) - log(16.0)) / 15.0);
    for (int i = 0; i < 16; i++) {
        double r = floor(16.0 * pow(factor, (double)i));
        prm.icell[i] = (float)(r * 0.5);
        prm.resm1[i] = (float)(r - 1.0);
    }

    int npts = in_sizes[xi] / 3;
    int pb = (npts + 255) / 256;

    void* histp = nullptr;
    cudaGetSymbolAddress(&histp, d_hist);
    cudaMemsetAsync(histp, 0, NB * sizeof(unsigned), 0);

    k_hist<<<pb, 256>>>(x, npts);
    k_scan1<<<NB / 256, 256>>>();
    k_scan3<<<NB / 256, 256>>>();
    k_scatter<<<pb, 256>>>(x, npts);
    hash_embed_kernel<<<pb, 256>>>(tbl, npts, prm);
    k_permute<<<(npts * 8 + 255) / 256, 256>>>(out, npts);
}